// round 11
// baseline (speedup 1.0000x reference)
#include <cuda_runtime.h>
#include <math.h>

#define BATCH 8
#define NQ    300
#define CH    256
#define NLVL  4
#define P_IN  32

__device__ __forceinline__ float warp_sum(float v) {
#pragma unroll
    for (int o = 16; o > 0; o >>= 1) v += __shfl_down_sync(0xffffffffu, v, o);
    return v;
}

// occ-8 / 32-reg target: this is what made the split gather kernel fast (R7).
__global__ __launch_bounds__(CH, 8)
void sampling3d_kernel(const float* __restrict__ f0,
                       const float* __restrict__ f1,
                       const float* __restrict__ f2,
                       const float* __restrict__ f3,
                       const float* __restrict__ qpos,
                       const float* __restrict__ qcont,
                       const float* __restrict__ Woff,
                       const float* __restrict__ boff,
                       const float* __restrict__ sigma_z,
                       float* __restrict__ out)
{
    const int idx = blockIdx.x;        // b*NQ + n
    const int t   = threadIdx.x;
    const int b   = idx / NQ;

    __shared__ __align__(16) float s_acc[CH];
    __shared__ float s_red[3][8];
    __shared__ float s_prm[8];         // sx, sy, zw0..3

    // ---- prep: offsets = qcont @ W_off + b_off (block reduction) ----
    {
        const float q = qcont[(size_t)idx * CH + t];
        float p0 = q * Woff[t * 3 + 0];
        float p1 = q * Woff[t * 3 + 1];
        float p2 = q * Woff[t * 3 + 2];
        p0 = warp_sum(p0); p1 = warp_sum(p1); p2 = warp_sum(p2);
        const int lane = t & 31, wid = t >> 5;
        if (lane == 0) { s_red[0][wid] = p0; s_red[1][wid] = p1; s_red[2][wid] = p2; }
    }
    __syncthreads();
    if (t == 0) {
        float dd[3];
#pragma unroll
        for (int k = 0; k < 3; k++) {
            float s = boff[k];
#pragma unroll
            for (int w = 0; w < 8; w++) s += s_red[k][w];
            dd[k] = s;
        }
        const float x = qpos[idx*4+0], y = qpos[idx*4+1];
        const float z = qpos[idx*4+2], r = qpos[idx*4+3];
        const float sx = x + dd[0] * exp2f(z - r);
        const float sy = y + dd[1] * exp2f(z + r);
        const float sz = z + dd[2];
        const float sig = sigma_z[0];
        const float invs = 1.0f / (2.0f * sig * sig);

        float g[NLVL], m = -1e30f;
#pragma unroll
        for (int l = 0; l < NLVL; l++) {
            const float d = sz - (float)l;
            g[l] = expf(-d * d * invs);
            m = fmaxf(m, g[l]);
        }
        float e[NLVL], se = 0.f;
#pragma unroll
        for (int l = 0; l < NLVL; l++) { e[l] = expf(g[l] - m); se += e[l]; }
        const float invse = 1.0f / se;
        s_prm[0] = sx; s_prm[1] = sy;
#pragma unroll
        for (int l = 0; l < NLVL; l++) s_prm[2 + l] = e[l] * invse;
    }
    __syncthreads();

    const float sx = s_prm[0], sy = s_prm[1];

    // ---- corner-in-lane gather: lane = 4*chan_group + corner ----
    const float* fptr[NLVL] = { f0, f1, f2, f3 };
    const int    HS[NLVL]   = { 100, 50, 25, 13 };

    const int corner = t & 3;          // 0:(y0,x0) 1:(y0,x1) 2:(y1,x0) 3:(y1,x1)
    const int cg     = t >> 2;         // channel group 0..63

    float acc0 = 0.f, acc1 = 0.f, acc2 = 0.f, acc3 = 0.f;
#pragma unroll
    for (int l = 0; l < NLVL; l++) {
        const int   H  = HS[l];
        const int   HH = H * H;
        const float fH = (float)H;
        const float px = fminf(fmaxf(sx - 0.5f, 0.0f), fH - 1.0f);
        const float py = fminf(fmaxf(sy - 0.5f, 0.0f), fH - 1.0f);
        const float x0f = floorf(px), y0f = floorf(py);
        const float wx = px - x0f, wy = py - y0f;
        const int x0 = (int)x0f, y0 = (int)y0f;
        const int x1 = min(x0 + 1, H - 1);
        const int y1 = min(y0 + 1, H - 1);

        const int   xsel = (corner & 1) ? x1 : x0;
        const int   ysel = (corner & 2) ? y1 : y0;
        const float wsel = ((corner & 1) ? wx : 1.0f - wx)
                         * ((corner & 2) ? wy : 1.0f - wy) * s_prm[2 + l];

        const float* base = fptr[l] + (size_t)b * CH * HH + ysel * H + xsel;
        acc0 += wsel * __ldg(base + (size_t)(cg      ) * HH);
        acc1 += wsel * __ldg(base + (size_t)(cg +  64) * HH);
        acc2 += wsel * __ldg(base + (size_t)(cg + 128) * HH);
        acc3 += wsel * __ldg(base + (size_t)(cg + 192) * HH);
    }

    // quad butterfly over the 4 corners
    acc0 += __shfl_xor_sync(0xffffffffu, acc0, 1);
    acc0 += __shfl_xor_sync(0xffffffffu, acc0, 2);
    acc1 += __shfl_xor_sync(0xffffffffu, acc1, 1);
    acc1 += __shfl_xor_sync(0xffffffffu, acc1, 2);
    acc2 += __shfl_xor_sync(0xffffffffu, acc2, 1);
    acc2 += __shfl_xor_sync(0xffffffffu, acc2, 2);
    acc3 += __shfl_xor_sync(0xffffffffu, acc3, 1);
    acc3 += __shfl_xor_sync(0xffffffffu, acc3, 2);

    if (corner == 0) {
        s_acc[cg      ] = acc0;
        s_acc[cg +  64] = acc1;
        s_acc[cg + 128] = acc2;
        s_acc[cg + 192] = acc3;
    }
    __syncthreads();

    // ---- broadcast to P_IN points, evict-first streaming stores ----
    const float4 v = ((const float4*)s_acc)[t & 63];
    float4* ov = (float4*)out + (size_t)idx * (P_IN * CH / 4);
#pragma unroll
    for (int i = 0; i < 8; i++)
        __stcs(&ov[t + i * CH], v);
}

extern "C" void kernel_launch(void* const* d_in, const int* in_sizes, int n_in,
                              void* d_out, int out_size)
{
    const float* f0    = (const float*)d_in[0];
    const float* f1    = (const float*)d_in[1];
    const float* f2    = (const float*)d_in[2];
    const float* f3    = (const float*)d_in[3];
    const float* qpos  = (const float*)d_in[4];
    const float* qcont = (const float*)d_in[5];
    const float* Woff  = (const float*)d_in[6];
    const float* boff  = (const float*)d_in[7];
    const float* sigz  = (const float*)d_in[8];
    float* out = (float*)d_out;

    sampling3d_kernel<<<BATCH * NQ, CH>>>(f0, f1, f2, f3, qpos, qcont,
                                          Woff, boff, sigz, out);
}

// round 12
// speedup vs baseline: 1.2177x; 1.2177x over previous
#include <cuda_runtime.h>
#include <math.h>

#define BATCH 8
#define NQ    300
#define CH    256
#define NLVL  4
#define P_IN  32

__global__ __launch_bounds__(CH, 8)
void sampling3d_kernel(const float* __restrict__ f0,
                       const float* __restrict__ f1,
                       const float* __restrict__ f2,
                       const float* __restrict__ f3,
                       const float* __restrict__ qpos,
                       const float* __restrict__ qcont,
                       const float* __restrict__ Woff,
                       const float* __restrict__ boff,
                       const float* __restrict__ sigma_z,
                       float* __restrict__ out)
{
    const int idx = blockIdx.x;        // b*NQ + n
    const int t   = threadIdx.x;
    const int b   = idx / NQ;

    __shared__ __align__(16) float s_acc[CH];
    __shared__ float s_prm[8];         // sx, sy, zw0..3

    // ---- prep confined to warp 0: projection + softmax ----
    // Spills (if any) at the 32-reg ceiling land here, once per CTA,
    // in one warp, hidden by the other 7 warps. Gather loop stays lean.
    if (t < 32) {
        const float4* q4 = (const float4*)(qcont + (size_t)idx * CH) + t * 2;
        float p0 = 0.f, p1 = 0.f, p2 = 0.f;
#pragma unroll
        for (int j = 0; j < 2; j++) {
            const float4 qv = q4[j];
            const int c = t * 8 + j * 4;
            p0 += qv.x * Woff[(c+0)*3+0] + qv.y * Woff[(c+1)*3+0]
                + qv.z * Woff[(c+2)*3+0] + qv.w * Woff[(c+3)*3+0];
            p1 += qv.x * Woff[(c+0)*3+1] + qv.y * Woff[(c+1)*3+1]
                + qv.z * Woff[(c+2)*3+1] + qv.w * Woff[(c+3)*3+1];
            p2 += qv.x * Woff[(c+0)*3+2] + qv.y * Woff[(c+1)*3+2]
                + qv.z * Woff[(c+2)*3+2] + qv.w * Woff[(c+3)*3+2];
        }
#pragma unroll
        for (int o = 16; o > 0; o >>= 1) {
            p0 += __shfl_xor_sync(0xffffffffu, p0, o);
            p1 += __shfl_xor_sync(0xffffffffu, p1, o);
            p2 += __shfl_xor_sync(0xffffffffu, p2, o);
        }
        if (t == 0) {
            const float dx = p0 + boff[0];
            const float dy = p1 + boff[1];
            const float dz = p2 + boff[2];
            const float x = qpos[idx*4+0], y = qpos[idx*4+1];
            const float z = qpos[idx*4+2], r = qpos[idx*4+3];
            const float sx = x + dx * exp2f(z - r);
            const float sy = y + dy * exp2f(z + r);
            const float sz = z + dz;
            const float sig = sigma_z[0];
            const float invs = 1.0f / (2.0f * sig * sig);

            float g[NLVL], m = -1e30f;
#pragma unroll
            for (int l = 0; l < NLVL; l++) {
                const float d = sz - (float)l;
                g[l] = expf(-d * d * invs);
                m = fmaxf(m, g[l]);
            }
            float e[NLVL], se = 0.f;
#pragma unroll
            for (int l = 0; l < NLVL; l++) { e[l] = expf(g[l] - m); se += e[l]; }
            const float invse = 1.0f / se;
            s_prm[0] = sx; s_prm[1] = sy;
#pragma unroll
            for (int l = 0; l < NLVL; l++) s_prm[2 + l] = e[l] * invse;
        }
    }
    __syncthreads();

    // ---- params into registers (R7-identical gather body follows) ----
    const float sx = s_prm[0], sy = s_prm[1];
    float zw[NLVL];
#pragma unroll
    for (int l = 0; l < NLVL; l++) zw[l] = s_prm[2 + l];

    const float* fptr[NLVL] = { f0, f1, f2, f3 };
    const int    HS[NLVL]   = { 100, 50, 25, 13 };

    const int corner = t & 3;          // 0:(y0,x0) 1:(y0,x1) 2:(y1,x0) 3:(y1,x1)
    const int cg     = t >> 2;         // channel group 0..63

    float acc0 = 0.f, acc1 = 0.f, acc2 = 0.f, acc3 = 0.f;
#pragma unroll
    for (int l = 0; l < NLVL; l++) {
        const int   H  = HS[l];
        const int   HH = H * H;
        const float fH = (float)H;
        const float px = fminf(fmaxf(sx - 0.5f, 0.0f), fH - 1.0f);
        const float py = fminf(fmaxf(sy - 0.5f, 0.0f), fH - 1.0f);
        const float x0f = floorf(px), y0f = floorf(py);
        const float wx = px - x0f, wy = py - y0f;
        const int x0 = (int)x0f, y0 = (int)y0f;
        const int x1 = min(x0 + 1, H - 1);
        const int y1 = min(y0 + 1, H - 1);

        const int   xsel = (corner & 1) ? x1 : x0;
        const int   ysel = (corner & 2) ? y1 : y0;
        const float wsel = ((corner & 1) ? wx : 1.0f - wx)
                         * ((corner & 2) ? wy : 1.0f - wy) * zw[l];

        const float* base = fptr[l] + (size_t)b * CH * HH + ysel * H + xsel;
        acc0 += wsel * __ldg(base + (size_t)(cg      ) * HH);
        acc1 += wsel * __ldg(base + (size_t)(cg +  64) * HH);
        acc2 += wsel * __ldg(base + (size_t)(cg + 128) * HH);
        acc3 += wsel * __ldg(base + (size_t)(cg + 192) * HH);
    }

    // quad butterfly over the 4 corners
    acc0 += __shfl_xor_sync(0xffffffffu, acc0, 1);
    acc0 += __shfl_xor_sync(0xffffffffu, acc0, 2);
    acc1 += __shfl_xor_sync(0xffffffffu, acc1, 1);
    acc1 += __shfl_xor_sync(0xffffffffu, acc1, 2);
    acc2 += __shfl_xor_sync(0xffffffffu, acc2, 1);
    acc2 += __shfl_xor_sync(0xffffffffu, acc2, 2);
    acc3 += __shfl_xor_sync(0xffffffffu, acc3, 1);
    acc3 += __shfl_xor_sync(0xffffffffu, acc3, 2);

    if (corner == 0) {
        s_acc[cg      ] = acc0;
        s_acc[cg +  64] = acc1;
        s_acc[cg + 128] = acc2;
        s_acc[cg + 192] = acc3;
    }
    __syncthreads();

    // ---- broadcast to P_IN points, evict-first streaming stores ----
    const float4 v = ((const float4*)s_acc)[t & 63];
    float4* ov = (float4*)out + (size_t)idx * (P_IN * CH / 4);
#pragma unroll
    for (int i = 0; i < 8; i++)
        __stcs(&ov[t + i * CH], v);
}

extern "C" void kernel_launch(void* const* d_in, const int* in_sizes, int n_in,
                              void* d_out, int out_size)
{
    const float* f0    = (const float*)d_in[0];
    const float* f1    = (const float*)d_in[1];
    const float* f2    = (const float*)d_in[2];
    const float* f3    = (const float*)d_in[3];
    const float* qpos  = (const float*)d_in[4];
    const float* qcont = (const float*)d_in[5];
    const float* Woff  = (const float*)d_in[6];
    const float* boff  = (const float*)d_in[7];
    const float* sigz  = (const float*)d_in[8];
    float* out = (float*)d_out;

    sampling3d_kernel<<<BATCH * NQ, CH>>>(f0, f1, f2, f3, qpos, qcont,
                                          Woff, boff, sigz, out);
}

// round 15
// speedup vs baseline: 1.2684x; 1.0416x over previous
#include <cuda_runtime.h>
#include <math.h>

#define BATCH 8
#define NQ    300
#define CH    256
#define NLVL  4
#define P_IN  32

__global__ __launch_bounds__(CH, 8)
void sampling3d_kernel(const float* __restrict__ f0,
                       const float* __restrict__ f1,
                       const float* __restrict__ f2,
                       const float* __restrict__ f3,
                       const float* __restrict__ qpos,
                       const float* __restrict__ qcont,
                       const float* __restrict__ Woff,
                       const float* __restrict__ boff,
                       const float* __restrict__ sigma_z,
                       float* __restrict__ out)
{
    const int idx = blockIdx.x;        // b*NQ + n
    const int t   = threadIdx.x;
    const int b   = idx / NQ;
    const int lane = t & 31;

    __shared__ __align__(16) float s_acc[CH];

    // ---- per-warp redundant prep: NO cross-warp barrier ----
    // Every warp computes the full 256->3 projection; lane covers 8 channels.
    float p0 = 0.f, p1 = 0.f, p2 = 0.f;
    {
        const float4* q4 = (const float4*)(qcont + (size_t)idx * CH) + lane * 2;
        const float4 qa = q4[0], qb = q4[1];
        const float qv[8] = { qa.x, qa.y, qa.z, qa.w, qb.x, qb.y, qb.z, qb.w };

        const float4* w4 = (const float4*)Woff + lane * 6;   // 24 floats/lane
        float w[24];
#pragma unroll
        for (int j = 0; j < 6; j++) {
            const float4 v = w4[j];
            w[4*j] = v.x; w[4*j+1] = v.y; w[4*j+2] = v.z; w[4*j+3] = v.w;
        }
#pragma unroll
        for (int j = 0; j < 8; j++) {
            p0 += qv[j] * w[3*j+0];
            p1 += qv[j] * w[3*j+1];
            p2 += qv[j] * w[3*j+2];
        }
    }
#pragma unroll
    for (int o = 16; o > 0; o >>= 1) {   // XOR butterfly: all lanes get sums
        p0 += __shfl_xor_sync(0xffffffffu, p0, o);
        p1 += __shfl_xor_sync(0xffffffffu, p1, o);
        p2 += __shfl_xor_sync(0xffffffffu, p2, o);
    }

    // scalar tail, redundantly per lane (SIMT: one pass)
    float sx, sy, zw[NLVL];
    {
        const float dx = p0 + boff[0];
        const float dy = p1 + boff[1];
        const float dz = p2 + boff[2];
        const float x = qpos[idx*4+0], y = qpos[idx*4+1];
        const float z = qpos[idx*4+2], r = qpos[idx*4+3];
        sx = x + dx * exp2f(z - r);
        sy = y + dy * exp2f(z + r);
        const float sz = z + dz;
        const float sig = sigma_z[0];
        const float invs = 1.0f / (2.0f * sig * sig);

        float g[NLVL], m = -1e30f;
#pragma unroll
        for (int l = 0; l < NLVL; l++) {
            const float d = sz - (float)l;
            g[l] = expf(-d * d * invs);
            m = fmaxf(m, g[l]);
        }
        float e[NLVL], se = 0.f;
#pragma unroll
        for (int l = 0; l < NLVL; l++) { e[l] = expf(g[l] - m); se += e[l]; }
        const float invse = 1.0f / se;
#pragma unroll
        for (int l = 0; l < NLVL; l++) zw[l] = e[l] * invse;
    }

    // ---- corner-in-lane gather (R7-identical body) ----
    const float* fptr[NLVL] = { f0, f1, f2, f3 };
    const int    HS[NLVL]   = { 100, 50, 25, 13 };

    const int corner = t & 3;          // 0:(y0,x0) 1:(y0,x1) 2:(y1,x0) 3:(y1,x1)
    const int cg     = t >> 2;         // channel group 0..63

    float acc0 = 0.f, acc1 = 0.f, acc2 = 0.f, acc3 = 0.f;
#pragma unroll
    for (int l = 0; l < NLVL; l++) {
        const int   H  = HS[l];
        const int   HH = H * H;
        const float fH = (float)H;
        const float px = fminf(fmaxf(sx - 0.5f, 0.0f), fH - 1.0f);
        const float py = fminf(fmaxf(sy - 0.5f, 0.0f), fH - 1.0f);
        const float x0f = floorf(px), y0f = floorf(py);
        const float wx = px - x0f, wy = py - y0f;
        const int x0 = (int)x0f, y0 = (int)y0f;
        const int x1 = min(x0 + 1, H - 1);
        const int y1 = min(y0 + 1, H - 1);

        const int   xsel = (corner & 1) ? x1 : x0;
        const int   ysel = (corner & 2) ? y1 : y0;
        const float wsel = ((corner & 1) ? wx : 1.0f - wx)
                         * ((corner & 2) ? wy : 1.0f - wy) * zw[l];

        const float* base = fptr[l] + (size_t)b * CH * HH + ysel * H + xsel;
        acc0 += wsel * __ldg(base + (size_t)(cg      ) * HH);
        acc1 += wsel * __ldg(base + (size_t)(cg +  64) * HH);
        acc2 += wsel * __ldg(base + (size_t)(cg + 128) * HH);
        acc3 += wsel * __ldg(base + (size_t)(cg + 192) * HH);
    }

    // quad butterfly over the 4 corners
    acc0 += __shfl_xor_sync(0xffffffffu, acc0, 1);
    acc0 += __shfl_xor_sync(0xffffffffu, acc0, 2);
    acc1 += __shfl_xor_sync(0xffffffffu, acc1, 1);
    acc1 += __shfl_xor_sync(0xffffffffu, acc1, 2);
    acc2 += __shfl_xor_sync(0xffffffffu, acc2, 1);
    acc2 += __shfl_xor_sync(0xffffffffu, acc2, 2);
    acc3 += __shfl_xor_sync(0xffffffffu, acc3, 1);
    acc3 += __shfl_xor_sync(0xffffffffu, acc3, 2);

    if (corner == 0) {
        s_acc[cg      ] = acc0;
        s_acc[cg +  64] = acc1;
        s_acc[cg + 128] = acc2;
        s_acc[cg + 192] = acc3;
    }
    __syncthreads();   // only barrier in the kernel

    // ---- broadcast to P_IN points, evict-first streaming stores ----
    const float4 v = ((const float4*)s_acc)[t & 63];
    float4* ov = (float4*)out + (size_t)idx * (P_IN * CH / 4);
#pragma unroll
    for (int i = 0; i < 8; i++)
        __stcs(&ov[t + i * CH], v);
}

extern "C" void kernel_launch(void* const* d_in, const int* in_sizes, int n_in,
                              void* d_out, int out_size)
{
    const float* f0    = (const float*)d_in[0];
    const float* f1    = (const float*)d_in[1];
    const float* f2    = (const float*)d_in[2];
    const float* f3    = (const float*)d_in[3];
    const float* qpos  = (const float*)d_in[4];
    const float* qcont = (const float*)d_in[5];
    const float* Woff  = (const float*)d_in[6];
    const float* boff  = (const float*)d_in[7];
    const float* sigz  = (const float*)d_in[8];
    float* out = (float*)d_out;

    sampling3d_kernel<<<BATCH * NQ, CH>>>(f0, f1, f2, f3, qpos, qcont,
                                          Woff, boff, sigz, out);
}